// round 4
// baseline (speedup 1.0000x reference)
#include <cuda_runtime.h>
#include <math.h>

#define B_   8
#define C_   64
#define H_   256
#define W_   256
#define LD_  8
#define MEM_ 128
#define BG_  2                   // batches per group (L2 tile)
#define NG_  (B_ / BG_)          // 4 groups
#define HCHUNK_ 32               // h rows per reduce block
#define NQ_  (H_ / HCHUNK_)      // 8 chunks per plane
#define GBLK_ (BG_ * C_ * NQ_)   // 1024 blocks per reduce/apply launch
#define GROWS_ (BG_ * W_)        // 512 gate rows per group

// Scratch (allocation-free per harness rules)
__device__ float g_part[B_ * C_ * NQ_ * W_];  // per-chunk partial h-sums (4 MB)
__device__ float g_gateT[B_ * C_ * W_];       // gate*mu, transposed [bc][w] (0.5 MB)

// ---------------------------------------------------------------------------
// Kernel 1: partial sums over 32-row h-chunks of the planes in group g.
// Plain cached loads: this pass is what makes x[group] L2-resident for apply.
// ---------------------------------------------------------------------------
__global__ __launch_bounds__(256) void reduce_h_partial_kernel(
    const float* __restrict__ x, int g)
{
    const int bcq_l = blockIdx.x;               // 0 .. GBLK_-1
    const int bc    = g * BG_ * C_ + (bcq_l >> 3);
    const int q     = bcq_l & (NQ_ - 1);

    const int t  = threadIdx.x;
    const int w4 = t & 63;                      // float4 column 0..63
    const int hs = t >> 6;                      // h-subgroup 0..3

    const float4* __restrict__ xp =
        (const float4*)(x + (size_t)bc * (H_ * W_) + (size_t)q * HCHUNK_ * W_);

    float4 s = make_float4(0.f, 0.f, 0.f, 0.f);
#pragma unroll
    for (int k = 0; k < HCHUNK_ / 4; ++k) {
        float4 v = xp[(size_t)(hs + 4 * k) * (W_ / 4) + w4];
        s.x += v.x; s.y += v.y; s.z += v.z; s.w += v.w;
    }

    __shared__ float4 red[256];
    red[t] = s;
    __syncthreads();
    if (hs == 0) {
        float4 a = red[t], b1 = red[t + 64], c1 = red[t + 128], d = red[t + 192];
        a.x += b1.x + c1.x + d.x;
        a.y += b1.y + c1.y + d.y;
        a.z += b1.z + c1.z + d.z;
        a.w += b1.w + c1.w + d.w;
        __stcs(&((float4*)g_part)[((size_t)bc * NQ_ + q) * (W_ / 4) + w4], a);
    }
}

// ---------------------------------------------------------------------------
// Kernel 2: per-row gating MLP + memory-bank attention for group g.
// Warp per row (b,w). Combines NQ_ h-partials on the fly; writes transposed.
// ---------------------------------------------------------------------------
__global__ __launch_bounds__(256) void gate_kernel(
    const float* __restrict__ w_sub, const float* __restrict__ b_sub,
    const float* __restrict__ w_up,  const float* __restrict__ b_up,
    const float* __restrict__ mb,    const float* __restrict__ mu, int g)
{
    __shared__ float s_wsub[C_ * LD_];
    __shared__ float s_mb[LD_ * MEM_];
    __shared__ float s_wup[LD_ * C_];
    __shared__ float s_bsub[LD_];
    __shared__ float s_bup[C_];

    const int tid = threadIdx.x;
    for (int i = tid; i < C_ * LD_;   i += blockDim.x) s_wsub[i] = w_sub[i];
    for (int i = tid; i < LD_ * MEM_; i += blockDim.x) s_mb[i]   = mb[i];
    for (int i = tid; i < LD_ * C_;   i += blockDim.x) s_wup[i]  = w_up[i];
    if (tid < LD_) s_bsub[tid] = b_sub[tid];
    if (tid < C_)  s_bup[tid]  = b_up[tid];
    __syncthreads();

    const float muv = mu[0];
    const int warp  = tid >> 5;
    const int lane  = tid & 31;
    const int rloc  = blockIdx.x * (blockDim.x >> 5) + warp;  // 0 .. GROWS_-1
    if (rloc >= GROWS_) return;

    const int b = g * BG_ + rloc / W_;
    const int w = rloc % W_;

    float low[LD_];
#pragma unroll
    for (int j = 0; j < LD_; ++j) low[j] = s_bsub[j];

    const float inv_h = 1.0f / H_;
#pragma unroll 4
    for (int c = 0; c < C_; ++c) {
        const float* pp = g_part + ((size_t)(b * C_ + c) * NQ_) * W_ + w;
        float yv = 0.f;
#pragma unroll
        for (int q = 0; q < NQ_; ++q) yv += __ldcs(pp + q * W_);
        yv *= inv_h;
#pragma unroll
        for (int j = 0; j < LD_; ++j)
            low[j] = fmaf(yv, s_wsub[c * LD_ + j], low[j]);
    }

    const float scale = rsqrtf((float)LD_);
    float f1[4];
#pragma unroll
    for (int k = 0; k < 4; ++k) {
        const int m = lane + 32 * k;
        float acc = 0.f;
#pragma unroll
        for (int j = 0; j < LD_; ++j)
            acc = fmaf(low[j], s_mb[j * MEM_ + m], acc);
        f1[k] = acc * scale;
    }

    float mx = fmaxf(fmaxf(f1[0], f1[1]), fmaxf(f1[2], f1[3]));
#pragma unroll
    for (int off = 16; off > 0; off >>= 1)
        mx = fmaxf(mx, __shfl_xor_sync(0xffffffffu, mx, off));
    float e[4], sum = 0.f;
#pragma unroll
    for (int k = 0; k < 4; ++k) { e[k] = expf(f1[k] - mx); sum += e[k]; }
#pragma unroll
    for (int off = 16; off > 0; off >>= 1)
        sum += __shfl_xor_sync(0xffffffffu, sum, off);
    const float inv = 1.0f / sum;

    float y1[LD_];
#pragma unroll
    for (int j = 0; j < LD_; ++j) {
        float acc = 0.f;
#pragma unroll
        for (int k = 0; k < 4; ++k)
            acc = fmaf(e[k] * inv, s_mb[j * MEM_ + lane + 32 * k], acc);
#pragma unroll
        for (int off = 16; off > 0; off >>= 1)
            acc += __shfl_xor_sync(0xffffffffu, acc, off);
        y1[j] = acc;
    }

#pragma unroll
    for (int k = 0; k < 2; ++k) {
        const int c = lane + 32 * k;
        float acc = s_bup[c];
#pragma unroll
        for (int j = 0; j < LD_; ++j)
            acc = fmaf(y1[j], s_wup[j * C_ + c], acc);
        const float gt = 1.0f / (1.0f + expf(-acc));
        g_gateT[(size_t)(b * C_ + c) * W_ + w] = gt * muv;
    }
}

// ---------------------------------------------------------------------------
// Kernel 3: out = x * gate for group g. x reads should hit L2 (streamed there
// by reduce of the same group). Streaming stores for out keep x resident.
// ---------------------------------------------------------------------------
__global__ __launch_bounds__(256) void apply_gate_kernel(
    const float* __restrict__ x, float* __restrict__ out, int g)
{
    const int bcq_l = blockIdx.x;
    const int bc    = g * BG_ * C_ + (bcq_l >> 3);
    const int q     = bcq_l & (NQ_ - 1);

    __shared__ float gt[W_];
    for (int w = threadIdx.x; w < W_; w += blockDim.x)
        gt[w] = g_gateT[(size_t)bc * W_ + w];
    __syncthreads();

    const size_t base = (size_t)bc * (H_ * W_) + (size_t)q * HCHUNK_ * W_;
    const float4* __restrict__ xp = (const float4*)(x + base);
    float4*       __restrict__ op = (float4*)(out + base);

    const int n4 = HCHUNK_ * W_ / 4;      // 2048
#pragma unroll 8
    for (int i = threadIdx.x; i < n4; i += 256) {
        float4 v = xp[i];                          // expect L2 hit
        const int w4 = (i & (W_ / 4 - 1)) << 2;
        v.x *= gt[w4 + 0];
        v.y *= gt[w4 + 1];
        v.z *= gt[w4 + 2];
        v.w *= gt[w4 + 3];
        __stcs(&op[i], v);                         // streaming store
    }
}

extern "C" void kernel_launch(void* const* d_in, const int* in_sizes, int n_in,
                              void* d_out, int out_size) {
    const float* x     = (const float*)d_in[0];
    const float* w_sub = (const float*)d_in[1];
    const float* b_sub = (const float*)d_in[2];
    const float* w_up  = (const float*)d_in[3];
    const float* b_up  = (const float*)d_in[4];
    const float* mb    = (const float*)d_in[5];
    const float* mu    = (const float*)d_in[6];
    float* out = (float*)d_out;

    for (int g = 0; g < NG_; ++g) {
        reduce_h_partial_kernel<<<GBLK_, 256>>>(x, g);
        gate_kernel<<<GROWS_ / 8, 256>>>(w_sub, b_sub, w_up, b_up, mb, mu, g);
        apply_gate_kernel<<<GBLK_, 256>>>(x, out, g);
    }
}

// round 5
// speedup vs baseline: 1.7878x; 1.7878x over previous
#include <cuda_runtime.h>
#include <math.h>

#define B_   8
#define C_   64
#define H_   256
#define W_   256
#define LD_  8
#define MEM_ 128
#define NROWS_ (B_ * W_)    // 2048
#define HCHUNK_ 64          // h rows per reduce/apply block
#define NQ_ (H_ / HCHUNK_)  // 4 chunks per plane
#define NBLK_ (B_ * C_ * NQ_)  // 2048

// Scratch (allocation-free per harness rules)
__device__ float g_part[B_ * C_ * NQ_ * W_];  // per-chunk partial h-sums (2 MB)
__device__ float g_gateT[B_ * C_ * W_];       // gate*mu, transposed [bc][w] (0.5 MB)

// ---------------------------------------------------------------------------
// Kernel 1: partial sum over a 64-row h-chunk of one (b,c) plane.
// Loads are explicitly batched 8-deep into registers to maximize MLP.
// ---------------------------------------------------------------------------
__global__ __launch_bounds__(256) void reduce_h_partial_kernel(const float* __restrict__ x) {
    const int bcq = blockIdx.x;           // 0 .. NBLK_-1
    const int bc  = bcq >> 2;
    const int q   = bcq & (NQ_ - 1);

    const int t  = threadIdx.x;
    const int w4 = t & 63;                // float4 column 0..63
    const int hs = t >> 6;                // h-subgroup 0..3

    const float4* __restrict__ xp =
        (const float4*)(x + (size_t)bc * (H_ * W_) + (size_t)q * HCHUNK_ * W_);

    float4 s0 = make_float4(0.f, 0.f, 0.f, 0.f);
    float4 s1 = make_float4(0.f, 0.f, 0.f, 0.f);

#pragma unroll
    for (int half = 0; half < 2; ++half) {
        float4 v[8];
#pragma unroll
        for (int k = 0; k < 8; ++k)
            v[k] = xp[(size_t)(hs + 4 * (half * 8 + k)) * (W_ / 4) + w4];
#pragma unroll
        for (int k = 0; k < 8; ++k) {
            if (k & 1) { s1.x += v[k].x; s1.y += v[k].y; s1.z += v[k].z; s1.w += v[k].w; }
            else       { s0.x += v[k].x; s0.y += v[k].y; s0.z += v[k].z; s0.w += v[k].w; }
        }
    }
    float4 s = make_float4(s0.x + s1.x, s0.y + s1.y, s0.z + s1.z, s0.w + s1.w);

    __shared__ float4 red[256];
    red[t] = s;
    __syncthreads();
    if (hs == 0) {
        float4 a = red[t], b1 = red[t + 64], c1 = red[t + 128], d = red[t + 192];
        a.x += b1.x + c1.x + d.x;
        a.y += b1.y + c1.y + d.y;
        a.z += b1.z + c1.z + d.z;
        a.w += b1.w + c1.w + d.w;
        __stcs(&((float4*)g_part)[(size_t)bcq * (W_ / 4) + w4], a);
    }
}

// ---------------------------------------------------------------------------
// Kernel 2: per-row gating MLP + memory-bank attention. Warp per row (b,w).
// ---------------------------------------------------------------------------
__global__ __launch_bounds__(256) void gate_kernel(
    const float* __restrict__ w_sub, const float* __restrict__ b_sub,
    const float* __restrict__ w_up,  const float* __restrict__ b_up,
    const float* __restrict__ mb,    const float* __restrict__ mu)
{
    __shared__ float s_wsub[C_ * LD_];
    __shared__ float s_mb[LD_ * MEM_];
    __shared__ float s_wup[LD_ * C_];
    __shared__ float s_bsub[LD_];
    __shared__ float s_bup[C_];

    const int tid = threadIdx.x;
    for (int i = tid; i < C_ * LD_;   i += blockDim.x) s_wsub[i] = w_sub[i];
    for (int i = tid; i < LD_ * MEM_; i += blockDim.x) s_mb[i]   = mb[i];
    for (int i = tid; i < LD_ * C_;   i += blockDim.x) s_wup[i]  = w_up[i];
    if (tid < LD_) s_bsub[tid] = b_sub[tid];
    if (tid < C_)  s_bup[tid]  = b_up[tid];
    __syncthreads();

    const float muv = mu[0];
    const int warp = tid >> 5;
    const int lane = tid & 31;
    const int row  = blockIdx.x * (blockDim.x >> 5) + warp;
    if (row >= NROWS_) return;

    const int b = row / W_;
    const int w = row % W_;

    float low[LD_];
#pragma unroll
    for (int j = 0; j < LD_; ++j) low[j] = s_bsub[j];

    const float inv_h = 1.0f / H_;
#pragma unroll 4
    for (int c = 0; c < C_; ++c) {
        const float* pp = g_part + ((size_t)(b * C_ + c) * NQ_) * W_ + w;
        const float yv = (__ldcs(pp) + __ldcs(pp + W_) +
                          __ldcs(pp + 2 * W_) + __ldcs(pp + 3 * W_)) * inv_h;
#pragma unroll
        for (int j = 0; j < LD_; ++j)
            low[j] = fmaf(yv, s_wsub[c * LD_ + j], low[j]);
    }

    const float scale = rsqrtf((float)LD_);
    float f1[4];
#pragma unroll
    for (int k = 0; k < 4; ++k) {
        const int m = lane + 32 * k;
        float acc = 0.f;
#pragma unroll
        for (int j = 0; j < LD_; ++j)
            acc = fmaf(low[j], s_mb[j * MEM_ + m], acc);
        f1[k] = acc * scale;
    }

    float mx = fmaxf(fmaxf(f1[0], f1[1]), fmaxf(f1[2], f1[3]));
#pragma unroll
    for (int off = 16; off > 0; off >>= 1)
        mx = fmaxf(mx, __shfl_xor_sync(0xffffffffu, mx, off));
    float e[4], sum = 0.f;
#pragma unroll
    for (int k = 0; k < 4; ++k) { e[k] = expf(f1[k] - mx); sum += e[k]; }
#pragma unroll
    for (int off = 16; off > 0; off >>= 1)
        sum += __shfl_xor_sync(0xffffffffu, sum, off);
    const float inv = 1.0f / sum;

    float y1[LD_];
#pragma unroll
    for (int j = 0; j < LD_; ++j) {
        float acc = 0.f;
#pragma unroll
        for (int k = 0; k < 4; ++k)
            acc = fmaf(e[k] * inv, s_mb[j * MEM_ + lane + 32 * k], acc);
#pragma unroll
        for (int off = 16; off > 0; off >>= 1)
            acc += __shfl_xor_sync(0xffffffffu, acc, off);
        y1[j] = acc;
    }

#pragma unroll
    for (int k = 0; k < 2; ++k) {
        const int c = lane + 32 * k;
        float acc = s_bup[c];
#pragma unroll
        for (int j = 0; j < LD_; ++j)
            acc = fmaf(y1[j], s_wup[j * C_ + c], acc);
        const float g = 1.0f / (1.0f + expf(-acc));
        g_gateT[(size_t)(b * C_ + c) * W_ + w] = g * muv;
    }
}

// ---------------------------------------------------------------------------
// Kernel 3: out = x * gate. Each thread has a FIXED float4 column (idx & 63 is
// iteration-invariant), so its gate is one float4 register loaded once.
// Loads batched 8-deep; streaming stores. Reverse block order (minor L2 win).
// ---------------------------------------------------------------------------
__global__ __launch_bounds__(256) void apply_gate_kernel(
    const float* __restrict__ x, float* __restrict__ out)
{
    const int bcq = (NBLK_ - 1) - blockIdx.x;   // reverse order
    const int bc  = bcq >> 2;
    const int q   = bcq & (NQ_ - 1);

    const int t   = threadIdx.x;
    const int w4  = t & 63;                     // fixed float4 column
    const int hs  = t >> 6;                     // base h-subrow 0..3

    const float4 gv = __ldg(&((const float4*)(g_gateT + (size_t)bc * W_))[w4]);

    const size_t base = (size_t)bc * (H_ * W_) + (size_t)q * HCHUNK_ * W_;
    const float4* __restrict__ xp = (const float4*)(x + base);
    float4*       __restrict__ op = (float4*)(out + base);

#pragma unroll
    for (int half = 0; half < 2; ++half) {
        float4 v[8];
#pragma unroll
        for (int k = 0; k < 8; ++k)
            v[k] = __ldcs(&xp[(size_t)(hs + 4 * (half * 8 + k)) * (W_ / 4) + w4]);
#pragma unroll
        for (int k = 0; k < 8; ++k) {
            v[k].x *= gv.x; v[k].y *= gv.y; v[k].z *= gv.z; v[k].w *= gv.w;
            __stcs(&op[(size_t)(hs + 4 * (half * 8 + k)) * (W_ / 4) + w4], v[k]);
        }
    }
}

extern "C" void kernel_launch(void* const* d_in, const int* in_sizes, int n_in,
                              void* d_out, int out_size) {
    const float* x     = (const float*)d_in[0];
    const float* w_sub = (const float*)d_in[1];
    const float* b_sub = (const float*)d_in[2];
    const float* w_up  = (const float*)d_in[3];
    const float* b_up  = (const float*)d_in[4];
    const float* mb    = (const float*)d_in[5];
    const float* mu    = (const float*)d_in[6];
    float* out = (float*)d_out;

    reduce_h_partial_kernel<<<NBLK_, 256>>>(x);
    gate_kernel<<<NROWS_ / 8, 256>>>(w_sub, b_sub, w_up, b_up, mb, mu);
    apply_gate_kernel<<<NBLK_, 256>>>(x, out);
}

// round 6
// speedup vs baseline: 1.9421x; 1.0863x over previous
#include <cuda_runtime.h>
#include <math.h>

#define B_   8
#define C_   64
#define H_   256
#define W_   256
#define LD_  8
#define MEM_ 128
#define NROWS_ (B_ * W_)    // 2048
#define HCHUNK_ 64          // h rows per reduce/apply block
#define NQ_ (H_ / HCHUNK_)  // 4 chunks per plane
#define NBLK_ (B_ * C_ * NQ_)  // 2048

// Scratch (allocation-free per harness rules)
// Partials TRANSPOSED for the consumer: [b][w][c][q], so each gate row reads
// 256 contiguous floats. Writers of one 32B sector merge in write-back L2.
__device__ float g_partT[B_ * W_ * C_ * NQ_];  // 2 MB
__device__ float g_gateT[B_ * C_ * W_];        // gate*mu, [bc][w] (0.5 MB)

// ---------------------------------------------------------------------------
// Kernel 1: partial sum over a 64-row h-chunk of one (b,c) plane.
// ---------------------------------------------------------------------------
__global__ __launch_bounds__(256) void reduce_h_partial_kernel(const float* __restrict__ x) {
    const int bcq = blockIdx.x;           // 0 .. NBLK_-1
    const int bc  = bcq >> 2;
    const int q   = bcq & (NQ_ - 1);

    const int t  = threadIdx.x;
    const int w4 = t & 63;                // float4 column 0..63
    const int hs = t >> 6;                // h-subgroup 0..3

    const float4* __restrict__ xp =
        (const float4*)(x + (size_t)bc * (H_ * W_) + (size_t)q * HCHUNK_ * W_);

    float4 s0 = make_float4(0.f, 0.f, 0.f, 0.f);
    float4 s1 = make_float4(0.f, 0.f, 0.f, 0.f);

#pragma unroll
    for (int half = 0; half < 2; ++half) {
        float4 v[8];
#pragma unroll
        for (int k = 0; k < 8; ++k)
            v[k] = xp[(size_t)(hs + 4 * (half * 8 + k)) * (W_ / 4) + w4];
#pragma unroll
        for (int k = 0; k < 8; ++k) {
            if (k & 1) { s1.x += v[k].x; s1.y += v[k].y; s1.z += v[k].z; s1.w += v[k].w; }
            else       { s0.x += v[k].x; s0.y += v[k].y; s0.z += v[k].z; s0.w += v[k].w; }
        }
    }
    float4 s = make_float4(s0.x + s1.x, s0.y + s1.y, s0.z + s1.z, s0.w + s1.w);

    __shared__ float4 red[256];
    red[t] = s;
    __syncthreads();
    if (hs == 0) {
        float4 a = red[t], b1 = red[t + 64], c1 = red[t + 128], d = red[t + 192];
        a.x += b1.x + c1.x + d.x;
        a.y += b1.y + c1.y + d.y;
        a.z += b1.z + c1.z + d.z;
        a.w += b1.w + c1.w + d.w;

        // Transposed scatter: [b][w][c][q]. 4B stores, 1KB apart; the 8 writers
        // of each 32B sector coalesce in L2 before writeback.
        const int b = bc / C_;
        const int c = bc % C_;
        const size_t stride = (size_t)C_ * NQ_;              // +1 in w
        size_t o = (((size_t)b * W_ + 4 * w4) * C_ + c) * NQ_ + q;
        g_partT[o]              = a.x;
        g_partT[o + stride]     = a.y;
        g_partT[o + 2 * stride] = a.z;
        g_partT[o + 3 * stride] = a.w;
    }
}

// ---------------------------------------------------------------------------
// Kernel 2: per-row gating MLP + memory-bank attention. Warp per row (b,w).
// Partials now read as 2 coalesced float4 loads per lane (mostly L2 hits).
// ---------------------------------------------------------------------------
__global__ __launch_bounds__(256) void gate_kernel(
    const float* __restrict__ w_sub, const float* __restrict__ b_sub,
    const float* __restrict__ w_up,  const float* __restrict__ b_up,
    const float* __restrict__ mb,    const float* __restrict__ mu)
{
    __shared__ float s_wsub[C_ * LD_];
    __shared__ float s_mb[LD_ * MEM_];
    __shared__ float s_wup[LD_ * C_];
    __shared__ float s_bsub[LD_];
    __shared__ float s_bup[C_];

    const int tid = threadIdx.x;
    for (int i = tid; i < C_ * LD_;   i += blockDim.x) s_wsub[i] = w_sub[i];
    for (int i = tid; i < LD_ * MEM_; i += blockDim.x) s_mb[i]   = mb[i];
    for (int i = tid; i < LD_ * C_;   i += blockDim.x) s_wup[i]  = w_up[i];
    if (tid < LD_) s_bsub[tid] = b_sub[tid];
    if (tid < C_)  s_bup[tid]  = b_up[tid];
    __syncthreads();

    const float muv = mu[0];
    const int warp = tid >> 5;
    const int lane = tid & 31;
    const int row  = blockIdx.x * (blockDim.x >> 5) + warp;
    if (row >= NROWS_) return;

    const int b = row / W_;
    const int w = row % W_;

    // Pooled means: lane owns c = lane and c = lane+32. Each is one float4
    // (the 4 q-partials), contiguous per row -> fully coalesced.
    const float4* __restrict__ yp = (const float4*)(g_partT + (size_t)row * (C_ * NQ_));
    const float4 pa = yp[lane];
    const float4 pb = yp[lane + 32];
    const float inv_h = 1.0f / H_;
    const float yA = (pa.x + pa.y + pa.z + pa.w) * inv_h;   // y[lane]
    const float yB = (pb.x + pb.y + pb.z + pb.w) * inv_h;   // y[lane+32]

    // low[j] = b_sub[j] + sum_c y[c] * w_sub[c][j]  (warp-reduced)
    float low[LD_];
#pragma unroll
    for (int j = 0; j < LD_; ++j) {
        float p = fmaf(yA, s_wsub[lane * LD_ + j],
                       yB * s_wsub[(lane + 32) * LD_ + j]);
#pragma unroll
        for (int off = 16; off > 0; off >>= 1)
            p += __shfl_xor_sync(0xffffffffu, p, off);
        low[j] = p + s_bsub[j];
    }

    const float scale = rsqrtf((float)LD_);
    float f1[4];
#pragma unroll
    for (int k = 0; k < 4; ++k) {
        const int m = lane + 32 * k;
        float acc = 0.f;
#pragma unroll
        for (int j = 0; j < LD_; ++j)
            acc = fmaf(low[j], s_mb[j * MEM_ + m], acc);
        f1[k] = acc * scale;
    }

    float mx = fmaxf(fmaxf(f1[0], f1[1]), fmaxf(f1[2], f1[3]));
#pragma unroll
    for (int off = 16; off > 0; off >>= 1)
        mx = fmaxf(mx, __shfl_xor_sync(0xffffffffu, mx, off));
    float e[4], sum = 0.f;
#pragma unroll
    for (int k = 0; k < 4; ++k) { e[k] = expf(f1[k] - mx); sum += e[k]; }
#pragma unroll
    for (int off = 16; off > 0; off >>= 1)
        sum += __shfl_xor_sync(0xffffffffu, sum, off);
    const float inv = 1.0f / sum;

    float y1[LD_];
#pragma unroll
    for (int j = 0; j < LD_; ++j) {
        float acc = 0.f;
#pragma unroll
        for (int k = 0; k < 4; ++k)
            acc = fmaf(e[k] * inv, s_mb[j * MEM_ + lane + 32 * k], acc);
#pragma unroll
        for (int off = 16; off > 0; off >>= 1)
            acc += __shfl_xor_sync(0xffffffffu, acc, off);
        y1[j] = acc;
    }

#pragma unroll
    for (int k = 0; k < 2; ++k) {
        const int c = lane + 32 * k;
        float acc = s_bup[c];
#pragma unroll
        for (int j = 0; j < LD_; ++j)
            acc = fmaf(y1[j], s_wup[j * C_ + c], acc);
        const float g = 1.0f / (1.0f + expf(-acc));
        g_gateT[(size_t)(b * C_ + c) * W_ + w] = g * muv;
    }
}

// ---------------------------------------------------------------------------
// Kernel 3: out = x * gate. Thread's float4 column is fixed -> gate is one
// float4 register. Loads batched 8-deep; streaming stores; reverse block order.
// ---------------------------------------------------------------------------
__global__ __launch_bounds__(256) void apply_gate_kernel(
    const float* __restrict__ x, float* __restrict__ out)
{
    const int bcq = (NBLK_ - 1) - blockIdx.x;   // reverse order
    const int bc  = bcq >> 2;
    const int q   = bcq & (NQ_ - 1);

    const int t   = threadIdx.x;
    const int w4  = t & 63;
    const int hs  = t >> 6;

    const float4 gv = __ldg(&((const float4*)(g_gateT + (size_t)bc * W_))[w4]);

    const size_t base = (size_t)bc * (H_ * W_) + (size_t)q * HCHUNK_ * W_;
    const float4* __restrict__ xp = (const float4*)(x + base);
    float4*       __restrict__ op = (float4*)(out + base);

#pragma unroll
    for (int half = 0; half < 2; ++half) {
        float4 v[8];
#pragma unroll
        for (int k = 0; k < 8; ++k)
            v[k] = __ldcs(&xp[(size_t)(hs + 4 * (half * 8 + k)) * (W_ / 4) + w4]);
#pragma unroll
        for (int k = 0; k < 8; ++k) {
            v[k].x *= gv.x; v[k].y *= gv.y; v[k].z *= gv.z; v[k].w *= gv.w;
            __stcs(&op[(size_t)(hs + 4 * (half * 8 + k)) * (W_ / 4) + w4], v[k]);
        }
    }
}

extern "C" void kernel_launch(void* const* d_in, const int* in_sizes, int n_in,
                              void* d_out, int out_size) {
    const float* x     = (const float*)d_in[0];
    const float* w_sub = (const float*)d_in[1];
    const float* b_sub = (const float*)d_in[2];
    const float* w_up  = (const float*)d_in[3];
    const float* b_up  = (const float*)d_in[4];
    const float* mb    = (const float*)d_in[5];
    const float* mu    = (const float*)d_in[6];
    float* out = (float*)d_out;

    reduce_h_partial_kernel<<<NBLK_, 256>>>(x);
    gate_kernel<<<NROWS_ / 8, 256>>>(w_sub, b_sub, w_up, b_up, mb, mu);
    apply_gate_kernel<<<NBLK_, 256>>>(x, out);
}